// round 4
// baseline (speedup 1.0000x reference)
#include <cuda_runtime.h>
#include <string.h>

#define LEAK 0.1f
#define BN_EPSF 1e-5f

#define BB     16
#define NWAY   5
#define NSHOT  5
#define NQ     150
#define CC     64
#define HWSZ   25
#define NSAMP_Q (BB*NQ)        // 2400
#define NSAMP_P (BB*NWAY)      // 80
#define NPAIR  (NSAMP_Q*NWAY)  // 12000
#define NHID   300
#define NHP    160             // padded hidden pairs (320 units)
#define MLP_ROWS 64
#define MLP_GRID ((NPAIR + MLP_ROWS - 1) / MLP_ROWS)   // 188

// ---------------- scratch ----------------------------------------------------
__device__ float  g_protos[NSAMP_P * CC * HWSZ];
__device__ __align__(16) float2 g_wq2[CC * 9 * 32];
__device__ __align__(16) float2 g_wp2[CC * 9 * 32];
__device__ float2 g_shift2[32];
__device__ float2 g_cp[NSAMP_P * HWSZ * 32];
__device__ float  g_feat[(MLP_GRID * MLP_ROWS) * CC];   // padded rows (zero-init)
__device__ __align__(16) float2 g_w1p[CC * NHP];        // [k][hp], zero-padded
__device__ float2 g_b1p[NHP];
__device__ float2 g_w2p[NHP];

// ---------------- packed f32x2 FMA -------------------------------------------
__device__ __forceinline__ float2 ffma2(float2 a, float2 b, float2 c) {
    unsigned long long A, B, C, D;
    memcpy(&A, &a, 8); memcpy(&B, &b, 8); memcpy(&C, &c, 8);
    asm("fma.rn.f32x2 %0, %1, %2, %3;" : "=l"(D) : "l"(A), "l"(B), "l"(C));
    float2 d; memcpy(&d, &D, 8);
    return d;
}

// ---------------- K0: prep (weights repack + BN fold + protos + mlp pack) ----
#define PREP_BLOCKS 145
#define PROTO_BLOCKS 125
#define MLPP_BLOCKS 41
__global__ void prep_protos_kernel(const float* __restrict__ cw,
                                   const float* __restrict__ gamma,
                                   const float* __restrict__ beta,
                                   const float* __restrict__ mean,
                                   const float* __restrict__ var,
                                   const float* __restrict__ shot,
                                   const float* __restrict__ pseudo,
                                   const float* __restrict__ w1,
                                   const float* __restrict__ b1,
                                   const float* __restrict__ w2) {
    int bid = blockIdx.x;
    int tid = threadIdx.x;
    if (bid < PREP_BLOCKS) {
        int gid = bid * 256 + tid;
        const int total = CC * 9 * 32;
        if (gid < 2 * total) {
            int half = gid / total;
            int idx  = gid % total;
            int ic   = idx / (9 * 32);
            int k    = (idx / 32) % 9;
            int ocp  = idx & 31;
            int icf  = ic + half * 64;
            int oc0 = 2 * ocp, oc1 = oc0 + 1;
            float s0 = gamma[oc0] * rsqrtf(var[oc0] + BN_EPSF);
            float s1 = gamma[oc1] * rsqrtf(var[oc1] + BN_EPSF);
            float2 wv = make_float2(cw[(oc0 * 128 + icf) * 9 + k] * s0,
                                    cw[(oc1 * 128 + icf) * 9 + k] * s1);
            if (half) g_wp2[idx] = wv; else g_wq2[idx] = wv;
        }
        if (gid < 32) {
            int oc0 = 2 * gid, oc1 = oc0 + 1;
            float s0 = gamma[oc0] * rsqrtf(var[oc0] + BN_EPSF);
            float s1 = gamma[oc1] * rsqrtf(var[oc1] + BN_EPSF);
            g_shift2[gid] = make_float2(beta[oc0] - mean[oc0] * s0,
                                        beta[oc1] - mean[oc1] * s1);
        }
    } else if (bid < PREP_BLOCKS + PROTO_BLOCKS) {
        int pid = (bid - PREP_BLOCKS) * 256 + tid;
        if (pid < NSAMP_P * 400) {
            int s = pid / 400;
            int j = pid - s * 400;
            const float4* sh = (const float4*)(shot   + (size_t)s * NSHOT * 1600) + j;
            const float4* ps = (const float4*)(pseudo + (size_t)s * NSHOT * 1600) + j;
            float4 a = make_float4(0.f, 0.f, 0.f, 0.f);
            #pragma unroll
            for (int k = 0; k < NSHOT; k++) {
                float4 v = sh[k * 400];
                a.x += v.x; a.y += v.y; a.z += v.z; a.w += v.w;
            }
            #pragma unroll
            for (int k = 0; k < NSHOT; k++) {
                float4 v = ps[k * 400];
                a.x += v.x; a.y += v.y; a.z += v.z; a.w += v.w;
            }
            a.x *= 0.1f; a.y *= 0.1f; a.z *= 0.1f; a.w *= 0.1f;
            ((float4*)g_protos)[pid] = a;
        }
    } else {
        int gid = (bid - PREP_BLOCKS - PROTO_BLOCKS) * 256 + tid;
        if (gid < CC * NHP) {
            int k = gid / NHP, j = gid - (gid / NHP) * NHP;
            float2 v = make_float2(0.f, 0.f);
            if (j < NHID / 2)
                v = make_float2(w1[k * NHID + 2 * j], w1[k * NHID + 2 * j + 1]);
            g_w1p[gid] = v;
        }
        if (gid < NHP) {
            int j = gid;
            float2 bv = make_float2(0.f, 0.f), wv = make_float2(0.f, 0.f);
            if (j < NHID / 2) {
                bv = make_float2(b1[2 * j], b1[2 * j + 1]);
                wv = make_float2(w2[2 * j], w2[2 * j + 1]);
            }
            g_b1p[j] = bv;
            g_w2p[j] = wv;
        }
    }
}

// ---------------- conv inner: one ic, exact taps, acc[25] --------------------
__device__ __forceinline__ void conv_ic(const float* __restrict__ xr,
                                        const float2 w[9], float2 acc[25]) {
    #pragma unroll
    for (int iy = 0; iy < 5; iy++) {
        float xv[5];
        #pragma unroll
        for (int j = 0; j < 5; j++) xv[j] = xr[iy * 5 + j];
        #pragma unroll
        for (int oy = 0; oy < 5; oy++) {
            int ky = iy - oy + 1;
            if (ky >= 0 && ky <= 2) {
                #pragma unroll
                for (int ox = 0; ox < 5; ox++) {
                    #pragma unroll
                    for (int kx = 0; kx < 3; kx++) {
                        int j = ox - 1 + kx;
                        if (j >= 0 && j < 5) {
                            float v = xv[j];
                            acc[oy * 5 + ox] =
                                ffma2(w[ky * 3 + kx], make_float2(v, v), acc[oy * 5 + ox]);
                        }
                    }
                }
            }
        }
    }
}

// ---------------- K1: conv on protos (R3 scheme: 2 samples x 4 ic-chunks) ----
__global__ void __launch_bounds__(256) convp_kernel() {
    __shared__ float2 red[2 * HWSZ * 32];
    int tid = threadIdx.x;
    int lane = tid & 31;
    int warp = tid >> 5;
    int sl = warp >> 2;
    int chunk = warp & 3;
    int s = blockIdx.x * 2 + sl;

    const float* xs = g_protos + (size_t)s * 1600;
    float2 acc[25];
    #pragma unroll
    for (int i = 0; i < 25; i++) acc[i] = make_float2(0.f, 0.f);

    #pragma unroll 1
    for (int icl = 0; icl < 16; icl++) {
        int ic = chunk * 16 + icl;
        const float2* wr = g_wp2 + ic * 288 + lane;
        float2 w[9];
        #pragma unroll
        for (int k = 0; k < 9; k++) w[k] = wr[k * 32];
        conv_ic(xs + ic * 25, w, acc);
    }

    float2* rb = red + (sl * HWSZ) * 32 + lane;
    if (chunk == 0) {
        #pragma unroll
        for (int p = 0; p < 25; p++) rb[p * 32] = acc[p];
    }
    __syncthreads();
    if (chunk == 1) {
        #pragma unroll
        for (int p = 0; p < 25; p++) {
            float2 t = rb[p * 32]; t.x += acc[p].x; t.y += acc[p].y; rb[p * 32] = t;
        }
    }
    __syncthreads();
    if (chunk == 2) {
        #pragma unroll
        for (int p = 0; p < 25; p++) {
            float2 t = rb[p * 32]; t.x += acc[p].x; t.y += acc[p].y; rb[p * 32] = t;
        }
    }
    __syncthreads();
    if (chunk == 3) {
        float2 sh = g_shift2[lane];
        #pragma unroll
        for (int p = 0; p < 25; p++) {
            float2 t = rb[p * 32];
            t.x += acc[p].x + sh.x;
            t.y += acc[p].y + sh.y;
            g_cp[(s * HWSZ + p) * 32 + lane] = t;
        }
    }
}

// ---------------- K2: conv on queries, 3 blocks/SM, single wave --------------
__global__ void __launch_bounds__(256, 3) convq_kernel(const float* __restrict__ xq) {
    __shared__ __align__(16) float2 sw[16 * 9 * 32];   // 36.9 KB
    int tid = threadIdx.x;
    int lane = tid & 31;
    int warp = tid >> 5;
    int s = blockIdx.x * 8 + warp;
    const float* xs = xq + (size_t)s * 1600;

    float2 acc[25];
    #pragma unroll
    for (int i = 0; i < 25; i++) acc[i] = make_float2(0.f, 0.f);

    #pragma unroll 1
    for (int ch = 0; ch < 4; ch++) {
        __syncthreads();
        {
            const float4* src4 = (const float4*)(g_wq2 + ch * 16 * 288);
            float4* dst4 = (float4*)sw;
            #pragma unroll
            for (int i = 0; i < 9; i++)
                dst4[tid + i * 256] = src4[tid + i * 256];
        }
        __syncthreads();
        #pragma unroll 1
        for (int icl = 0; icl < 16; icl++) {
            const float2* wr = sw + icl * 288 + lane;
            float2 w[9];
            #pragma unroll
            for (int k = 0; k < 9; k++) w[k] = wr[k * 32];
            conv_ic(xs + (ch * 16 + icl) * 25, w, acc);
        }
    }

    int b = s / NQ;
    #pragma unroll 1
    for (int w = 0; w < NWAY; w++) {
        const float2* cp = g_cp + ((b * NWAY + w) * HWSZ) * 32 + lane;
        float ax = 0.f, ay = 0.f;
        #pragma unroll
        for (int p = 0; p < 25; p++) {
            float2 c = cp[p * 32];
            float x = acc[p].x + c.x; x = fmaxf(x, LEAK * x);
            float y = acc[p].y + c.y; y = fmaxf(y, LEAK * y);
            ax += x; ay += y;
        }
        ((float2*)g_feat)[((size_t)s * NWAY + w) * 32 + lane] =
            make_float2(ax * 0.04f, ay * 0.04f);
    }
}

// ---------------- K3: MLP, register-tiled: 64 rows/block, 5hp x 8rows/thread -
__global__ void __launch_bounds__(256, 2) mlp_kernel(const float* __restrict__ b2,
                                                     float* __restrict__ out) {
    __shared__ __align__(16) float fsT[64][72];   // 18 KB, padded rows
    int tid = threadIdx.x;
    int tx = tid & 31;        // hidden-lane
    int ty = tid >> 5;        // row-group (8 rows each)
    int s0 = blockIdx.x * MLP_ROWS;

    for (int i = tid; i < MLP_ROWS * 64; i += 256) {
        int r = i >> 6, c = i & 63;
        fsT[c][r] = g_feat[(size_t)(s0 + r) * CC + c];
    }
    __syncthreads();

    float2 acc[5][8];
    #pragma unroll
    for (int p = 0; p < 5; p++)
        #pragma unroll
        for (int r = 0; r < 8; r++) acc[p][r] = make_float2(0.f, 0.f);

    #pragma unroll 2
    for (int k = 0; k < 64; k++) {
        float2 wv[5];
        #pragma unroll
        for (int p = 0; p < 5; p++) wv[p] = g_w1p[k * NHP + tx + 32 * p];
        const float4* fr = (const float4*)&fsT[k][ty * 8];
        float4 f0 = fr[0], f1 = fr[1];
        float fv[8] = {f0.x, f0.y, f0.z, f0.w, f1.x, f1.y, f1.z, f1.w};
        #pragma unroll
        for (int p = 0; p < 5; p++)
            #pragma unroll
            for (int r = 0; r < 8; r++)
                acc[p][r] = ffma2(wv[p], make_float2(fv[r], fv[r]), acc[p][r]);
    }

    float s[8];
    #pragma unroll
    for (int r = 0; r < 8; r++) s[r] = 0.f;
    #pragma unroll
    for (int p = 0; p < 5; p++) {
        float2 bv = g_b1p[tx + 32 * p];
        float2 wv = g_w2p[tx + 32 * p];
        #pragma unroll
        for (int r = 0; r < 8; r++) {
            float hx = acc[p][r].x + bv.x; hx = fmaxf(hx, LEAK * hx);
            float hy = acc[p][r].y + bv.y; hy = fmaxf(hy, LEAK * hy);
            s[r] += hx * wv.x + hy * wv.y;
        }
    }
    #pragma unroll
    for (int off = 16; off; off >>= 1)
        #pragma unroll
        for (int r = 0; r < 8; r++)
            s[r] += __shfl_down_sync(0xffffffffu, s[r], off);

    if (tx == 0) {
        float bb = b2[0];
        #pragma unroll
        for (int r = 0; r < 8; r++) {
            int row = s0 + ty * 8 + r;
            if (row < NPAIR)
                out[row] = 1.f / (1.f + expf(-(s[r] + bb)));
        }
    }
}

// ---------------- launch -----------------------------------------------------
extern "C" void kernel_launch(void* const* d_in, const int* in_sizes, int n_in,
                              void* d_out, int out_size) {
    const float* x_shot   = (const float*)d_in[0];
    const float* x_pseudo = (const float*)d_in[1];
    const float* x_query  = (const float*)d_in[2];
    const float* conv_w   = (const float*)d_in[3];
    const float* bn_gamma = (const float*)d_in[4];
    const float* bn_beta  = (const float*)d_in[5];
    const float* bn_mean  = (const float*)d_in[6];
    const float* bn_var   = (const float*)d_in[7];
    const float* w1       = (const float*)d_in[8];
    const float* b1       = (const float*)d_in[9];
    const float* w2       = (const float*)d_in[10];
    const float* b2       = (const float*)d_in[11];
    float* out = (float*)d_out;

    prep_protos_kernel<<<PREP_BLOCKS + PROTO_BLOCKS + MLPP_BLOCKS, 256>>>(
        conv_w, bn_gamma, bn_beta, bn_mean, bn_var, x_shot, x_pseudo, w1, b1, w2);
    convp_kernel<<<NSAMP_P / 2, 256>>>();
    convq_kernel<<<NSAMP_Q / 8, 256>>>(x_query);
    mlp_kernel<<<MLP_GRID, 256>>>(b2, out);
}

// round 6
// speedup vs baseline: 1.1171x; 1.1171x over previous
#include <cuda_runtime.h>
#include <string.h>

#define LEAK 0.1f
#define BN_EPSF 1e-5f

#define BB     16
#define NWAY   5
#define NSHOT  5
#define NQ     150
#define CC     64
#define HWSZ   25
#define NSAMP_Q (BB*NQ)        // 2400
#define NSAMP_P (BB*NWAY)      // 80
#define NPAIR  (NSAMP_Q*NWAY)  // 12000
#define NHID   300
#define NHP    160             // padded hidden pairs (320 units)

// ---------------- scratch ----------------------------------------------------
__device__ __align__(16) float2 g_wq2[CC * 9 * 32];   // [ic][tap][ocp], BN-scaled, oc-pair packed
__device__ __align__(16) float2 g_wp2[CC * 9 * 32];
__device__ float2 g_shift2[32];
__device__ float2 g_cp[NSAMP_P * HWSZ * 32];          // proto conv out [samp][pix][ocp]
__device__ float  g_feat[NPAIR * CC];
__device__ __align__(16) float2 g_w1p[CC * NHP];      // [k][hp], zero-padded
__device__ float2 g_b1p[NHP];
__device__ float2 g_w2p[NHP];

// ---------------- packed f32x2 FMA -------------------------------------------
__device__ __forceinline__ float2 ffma2(float2 a, float2 b, float2 c) {
    unsigned long long A, B, C, D;
    memcpy(&A, &a, 8); memcpy(&B, &b, 8); memcpy(&C, &c, 8);
    asm("fma.rn.f32x2 %0, %1, %2, %3;" : "=l"(D) : "l"(A), "l"(B), "l"(C));
    float2 d; memcpy(&d, &D, 8);
    return d;
}

// ---------------- K0: prep (conv weight repack + BN fold + mlp pack) ---------
#define PREP_BLOCKS 145
#define MLPP_BLOCKS 41
__global__ void prep_kernel(const float* __restrict__ cw,
                            const float* __restrict__ gamma,
                            const float* __restrict__ beta,
                            const float* __restrict__ mean,
                            const float* __restrict__ var,
                            const float* __restrict__ w1,
                            const float* __restrict__ b1,
                            const float* __restrict__ w2) {
    int bid = blockIdx.x;
    int tid = threadIdx.x;
    if (bid < PREP_BLOCKS) {
        int gid = bid * 256 + tid;
        const int total = CC * 9 * 32;
        if (gid < 2 * total) {
            int half = gid / total;
            int idx  = gid % total;
            int ic   = idx / (9 * 32);
            int k    = (idx / 32) % 9;
            int ocp  = idx & 31;
            int icf  = ic + half * 64;
            int oc0 = 2 * ocp, oc1 = oc0 + 1;
            float s0 = gamma[oc0] * rsqrtf(var[oc0] + BN_EPSF);
            float s1 = gamma[oc1] * rsqrtf(var[oc1] + BN_EPSF);
            float2 wv = make_float2(cw[(oc0 * 128 + icf) * 9 + k] * s0,
                                    cw[(oc1 * 128 + icf) * 9 + k] * s1);
            if (half) g_wp2[idx] = wv; else g_wq2[idx] = wv;
        }
        if (gid < 32) {
            int oc0 = 2 * gid, oc1 = oc0 + 1;
            float s0 = gamma[oc0] * rsqrtf(var[oc0] + BN_EPSF);
            float s1 = gamma[oc1] * rsqrtf(var[oc1] + BN_EPSF);
            g_shift2[gid] = make_float2(beta[oc0] - mean[oc0] * s0,
                                        beta[oc1] - mean[oc1] * s1);
        }
    } else {
        int gid = (bid - PREP_BLOCKS) * 256 + tid;
        if (gid < CC * NHP) {
            int k = gid / NHP, j = gid - (gid / NHP) * NHP;
            float2 v = make_float2(0.f, 0.f);
            if (j < NHID / 2)
                v = make_float2(w1[k * NHID + 2 * j], w1[k * NHID + 2 * j + 1]);
            g_w1p[gid] = v;
        }
        if (gid < NHP) {
            int j = gid;
            float2 bv = make_float2(0.f, 0.f), wv = make_float2(0.f, 0.f);
            if (j < NHID / 2) {
                bv = make_float2(b1[2 * j], b1[2 * j + 1]);
                wv = make_float2(w2[2 * j], w2[2 * j + 1]);
            }
            g_b1p[j] = bv;
            g_w2p[j] = wv;
        }
    }
}

// ---------------- conv inner: one ic, exact taps, acc[25] --------------------
__device__ __forceinline__ void conv_ic(const float* __restrict__ xr,
                                        const float2 w[9], float2 acc[25]) {
    #pragma unroll
    for (int iy = 0; iy < 5; iy++) {
        float xv[5];
        #pragma unroll
        for (int j = 0; j < 5; j++) xv[j] = xr[iy * 5 + j];
        #pragma unroll
        for (int oy = 0; oy < 5; oy++) {
            int ky = iy - oy + 1;
            if (ky >= 0 && ky <= 2) {
                #pragma unroll
                for (int ox = 0; ox < 5; ox++) {
                    #pragma unroll
                    for (int kx = 0; kx < 3; kx++) {
                        int j = ox - 1 + kx;
                        if (j >= 0 && j < 5) {
                            float v = xv[j];
                            acc[oy * 5 + ox] =
                                ffma2(w[ky * 3 + kx], make_float2(v, v), acc[oy * 5 + ox]);
                        }
                    }
                }
            }
        }
    }
}

// ---------------- K1: fused proto mean + conv (2 samples x 4 ic-chunks) ------
__global__ void __launch_bounds__(256) convp_kernel(const float* __restrict__ shot,
                                                    const float* __restrict__ pseudo) {
    __shared__ __align__(16) float sproto[2 * 1600];   // 12.8 KB
    __shared__ float2 red[2 * HWSZ * 32];              // 12.8 KB
    int tid = threadIdx.x;
    int lane = tid & 31;
    int warp = tid >> 5;
    int sl = warp >> 2;
    int chunk = warp & 3;
    int sBase = blockIdx.x * 2;

    // cooperative mean of 10 supports into sproto
    for (int it = tid; it < 800; it += 256) {
        int s = it / 400;
        int j = it - s * 400;
        const float4* sh = (const float4*)(shot   + (size_t)(sBase + s) * NSHOT * 1600) + j;
        const float4* ps = (const float4*)(pseudo + (size_t)(sBase + s) * NSHOT * 1600) + j;
        float4 a = make_float4(0.f, 0.f, 0.f, 0.f);
        #pragma unroll
        for (int k = 0; k < NSHOT; k++) {
            float4 v = sh[k * 400];
            a.x += v.x; a.y += v.y; a.z += v.z; a.w += v.w;
        }
        #pragma unroll
        for (int k = 0; k < NSHOT; k++) {
            float4 v = ps[k * 400];
            a.x += v.x; a.y += v.y; a.z += v.z; a.w += v.w;
        }
        a.x *= 0.1f; a.y *= 0.1f; a.z *= 0.1f; a.w *= 0.1f;
        ((float4*)sproto)[it] = a;
    }
    __syncthreads();

    const float* xs = sproto + sl * 1600;
    float2 acc[25];
    #pragma unroll
    for (int i = 0; i < 25; i++) acc[i] = make_float2(0.f, 0.f);

    #pragma unroll 1
    for (int icl = 0; icl < 16; icl++) {
        int ic = chunk * 16 + icl;
        const float2* wr = g_wp2 + ic * 288 + lane;
        float2 w[9];
        #pragma unroll
        for (int k = 0; k < 9; k++) w[k] = wr[k * 32];
        conv_ic(xs + ic * 25, w, acc);
    }

    float2* rb = red + (sl * HWSZ) * 32 + lane;
    if (chunk == 0) {
        #pragma unroll
        for (int p = 0; p < 25; p++) rb[p * 32] = acc[p];
    }
    __syncthreads();
    if (chunk == 1) {
        #pragma unroll
        for (int p = 0; p < 25; p++) {
            float2 t = rb[p * 32]; t.x += acc[p].x; t.y += acc[p].y; rb[p * 32] = t;
        }
    }
    __syncthreads();
    if (chunk == 2) {
        #pragma unroll
        for (int p = 0; p < 25; p++) {
            float2 t = rb[p * 32]; t.x += acc[p].x; t.y += acc[p].y; rb[p * 32] = t;
        }
    }
    __syncthreads();
    if (chunk == 3) {
        float2 sh = g_shift2[lane];
        #pragma unroll
        for (int p = 0; p < 25; p++) {
            float2 t = rb[p * 32];
            t.x += acc[p].x + sh.x;
            t.y += acc[p].y + sh.y;
            g_cp[((sBase + sl) * HWSZ + p) * 32 + lane] = t;
        }
    }
}

// ---------------- K2: conv on queries, smem x + weights (8-ic chunks), 3/SM --
__global__ void __launch_bounds__(256, 3) convq_kernel(const float* __restrict__ xq) {
    __shared__ __align__(16) float2 sw[8 * 9 * 32];    // 18.4 KB
    __shared__ __align__(16) float  sx[8 * 200];       // 6.4 KB (per-warp 8ic x 25)
    int tid = threadIdx.x;
    int lane = tid & 31;
    int warp = tid >> 5;
    int s = blockIdx.x * 8 + warp;
    const float4* xsrc = (const float4*)(xq + (size_t)s * 1600);
    float* myx = sx + warp * 200;

    float2 acc[25];
    #pragma unroll
    for (int i = 0; i < 25; i++) acc[i] = make_float2(0.f, 0.f);

    #pragma unroll 1
    for (int ch = 0; ch < 8; ch++) {
        __syncthreads();   // protect previous chunk reads of sw/sx
        {
            const float4* src4 = (const float4*)(g_wq2 + ch * 8 * 288);
            float4* dst4 = (float4*)sw;
            #pragma unroll
            for (int i = 0; i < 4; i++)
                dst4[tid + i * 256] = src4[tid + i * 256];   // 1024
            if (tid < 128) dst4[tid + 1024] = src4[tid + 1024];  // rest of 1152
        }
        {
            float4* dx = (float4*)myx;
            const float4* srcx = xsrc + ch * 50;
            #pragma unroll
            for (int i = 0; i < 2; i++) {
                int j = lane + i * 32;
                if (j < 50) dx[j] = srcx[j];
            }
        }
        __syncthreads();
        #pragma unroll 1
        for (int icl = 0; icl < 8; icl++) {
            const float2* wr = sw + icl * 288 + lane;
            float2 w[9];
            #pragma unroll
            for (int k = 0; k < 9; k++) w[k] = wr[k * 32];
            conv_ic(myx + icl * 25, w, acc);
        }
    }

    int b = s / NQ;
    #pragma unroll 1
    for (int w = 0; w < NWAY; w++) {
        const float2* cp = g_cp + ((b * NWAY + w) * HWSZ) * 32 + lane;
        float ax = 0.f, ay = 0.f;
        #pragma unroll
        for (int p = 0; p < 25; p++) {
            float2 c = cp[p * 32];
            float x = acc[p].x + c.x; x = fmaxf(x, LEAK * x);
            float y = acc[p].y + c.y; y = fmaxf(y, LEAK * y);
            ax += x; ay += y;
        }
        ((float2*)g_feat)[((size_t)s * NWAY + w) * 32 + lane] =
            make_float2(ax * 0.04f, ay * 0.04f);
    }
}

// ---------------- K3: MLP — smem weight chunks, 32 rows/block, grid 375 ------
#define MROWS 32
__global__ void __launch_bounds__(256, 3) mlp_kernel(const float* __restrict__ b2,
                                                     float* __restrict__ out) {
    __shared__ __align__(16) float  fsT[64][36];       // 9.2 KB
    __shared__ __align__(16) float2 sw1[16 * NHP];     // 20 KB per chunk
    int tid = threadIdx.x;
    int tx = tid & 31;        // hidden-lane
    int ty = tid >> 5;        // row-group (4 rows each)
    int s0 = blockIdx.x * MROWS;

    for (int i = tid; i < MROWS * 64; i += 256) {
        int r = i >> 6, c = i & 63;
        fsT[c][r] = g_feat[(size_t)(s0 + r) * CC + c];
    }

    float2 acc[5][4];
    #pragma unroll
    for (int p = 0; p < 5; p++)
        #pragma unroll
        for (int r = 0; r < 4; r++) acc[p][r] = make_float2(0.f, 0.f);

    #pragma unroll 1
    for (int ch = 0; ch < 4; ch++) {
        __syncthreads();
        {
            const float4* src4 = (const float4*)(g_w1p + ch * 16 * NHP);
            float4* dst4 = (float4*)sw1;
            #pragma unroll
            for (int i = 0; i < 5; i++)
                dst4[tid + i * 256] = src4[tid + i * 256];   // 1280 float4
        }
        __syncthreads();
        #pragma unroll 2
        for (int kl = 0; kl < 16; kl++) {
            int k = ch * 16 + kl;
            float2 wv[5];
            #pragma unroll
            for (int p = 0; p < 5; p++) wv[p] = sw1[kl * NHP + tx + 32 * p];
            const float4* fr = (const float4*)&fsT[k][ty * 4];
            float4 f = fr[0];
            float fv[4] = {f.x, f.y, f.z, f.w};
            #pragma unroll
            for (int p = 0; p < 5; p++)
                #pragma unroll
                for (int r = 0; r < 4; r++)
                    acc[p][r] = ffma2(wv[p], make_float2(fv[r], fv[r]), acc[p][r]);
        }
    }

    float s[4];
    #pragma unroll
    for (int r = 0; r < 4; r++) s[r] = 0.f;
    #pragma unroll
    for (int p = 0; p < 5; p++) {
        float2 bv = g_b1p[tx + 32 * p];
        float2 wv = g_w2p[tx + 32 * p];
        #pragma unroll
        for (int r = 0; r < 4; r++) {
            float hx = acc[p][r].x + bv.x; hx = fmaxf(hx, LEAK * hx);
            float hy = acc[p][r].y + bv.y; hy = fmaxf(hy, LEAK * hy);
            s[r] += hx * wv.x + hy * wv.y;
        }
    }
    #pragma unroll
    for (int off = 16; off; off >>= 1)
        #pragma unroll
        for (int r = 0; r < 4; r++)
            s[r] += __shfl_down_sync(0xffffffffu, s[r], off);

    if (tx == 0) {
        float bb = b2[0];
        #pragma unroll
        for (int r = 0; r < 4; r++)
            out[s0 + ty * 4 + r] = 1.f / (1.f + expf(-(s[r] + bb)));
    }
}

// ---------------- launch -----------------------------------------------------
extern "C" void kernel_launch(void* const* d_in, const int* in_sizes, int n_in,
                              void* d_out, int out_size) {
    const float* x_shot   = (const float*)d_in[0];
    const float* x_pseudo = (const float*)d_in[1];
    const float* x_query  = (const float*)d_in[2];
    const float* conv_w   = (const float*)d_in[3];
    const float* bn_gamma = (const float*)d_in[4];
    const float* bn_beta  = (const float*)d_in[5];
    const float* bn_mean  = (const float*)d_in[6];
    const float* bn_var   = (const float*)d_in[7];
    const float* w1       = (const float*)d_in[8];
    const float* b1       = (const float*)d_in[9];
    const float* w2       = (const float*)d_in[10];
    const float* b2       = (const float*)d_in[11];
    float* out = (float*)d_out;

    prep_kernel<<<PREP_BLOCKS + MLPP_BLOCKS, 256>>>(
        conv_w, bn_gamma, bn_beta, bn_mean, bn_var, w1, b1, w2);
    convp_kernel<<<NSAMP_P / 2, 256>>>(x_shot, x_pseudo);
    convq_kernel<<<NSAMP_Q / 8, 256>>>(x_query);
    mlp_kernel<<<NPAIR / MROWS, 256>>>(b2, out);
}

// round 7
// speedup vs baseline: 1.2679x; 1.1350x over previous
#include <cuda_runtime.h>
#include <string.h>

#define LEAK 0.1f
#define BN_EPSF 1e-5f

#define BB     16
#define NWAY   5
#define NSHOT  5
#define NQ     150
#define CC     64
#define HWSZ   25
#define NSAMP_Q (BB*NQ)        // 2400
#define NSAMP_P (BB*NWAY)      // 80
#define NPAIR  (NSAMP_Q*NWAY)  // 12000
#define NHID   300
#define NHP    160             // padded hidden pairs (320 units)

// ---------------- scratch ----------------------------------------------------
__device__ __align__(16) float2 g_wq2[CC * 9 * 32];   // [ic][tap][ocp], BN-scaled, oc-pair packed
__device__ __align__(16) float2 g_wp2[CC * 9 * 32];
__device__ float2 g_shift2[32];
__device__ float2 g_cp[NSAMP_P * HWSZ * 32];          // proto conv out [samp][pix][ocp]
__device__ float  g_feat[NPAIR * CC];
__device__ __align__(16) float2 g_w1p[CC * NHP];      // [k][hp], zero-padded
__device__ float2 g_b1p[NHP];
__device__ float2 g_w2p[NHP];

// ---------------- packed f32x2 FMA -------------------------------------------
__device__ __forceinline__ float2 ffma2(float2 a, float2 b, float2 c) {
    unsigned long long A, B, C, D;
    memcpy(&A, &a, 8); memcpy(&B, &b, 8); memcpy(&C, &c, 8);
    asm("fma.rn.f32x2 %0, %1, %2, %3;" : "=l"(D) : "l"(A), "l"(B), "l"(C));
    float2 d; memcpy(&d, &D, 8);
    return d;
}

// ---------------- K0: prep (conv weight repack + BN fold + mlp pack) ---------
#define PREP_BLOCKS 145
#define MLPP_BLOCKS 41
__global__ void prep_kernel(const float* __restrict__ cw,
                            const float* __restrict__ gamma,
                            const float* __restrict__ beta,
                            const float* __restrict__ mean,
                            const float* __restrict__ var,
                            const float* __restrict__ w1,
                            const float* __restrict__ b1,
                            const float* __restrict__ w2) {
    int bid = blockIdx.x;
    int tid = threadIdx.x;
    if (bid < PREP_BLOCKS) {
        int gid = bid * 256 + tid;
        const int total = CC * 9 * 32;
        if (gid < 2 * total) {
            int half = gid / total;
            int idx  = gid % total;
            int ic   = idx / (9 * 32);
            int k    = (idx / 32) % 9;
            int ocp  = idx & 31;
            int icf  = ic + half * 64;
            int oc0 = 2 * ocp, oc1 = oc0 + 1;
            float s0 = gamma[oc0] * rsqrtf(var[oc0] + BN_EPSF);
            float s1 = gamma[oc1] * rsqrtf(var[oc1] + BN_EPSF);
            float2 wv = make_float2(cw[(oc0 * 128 + icf) * 9 + k] * s0,
                                    cw[(oc1 * 128 + icf) * 9 + k] * s1);
            if (half) g_wp2[idx] = wv; else g_wq2[idx] = wv;
        }
        if (gid < 32) {
            int oc0 = 2 * gid, oc1 = oc0 + 1;
            float s0 = gamma[oc0] * rsqrtf(var[oc0] + BN_EPSF);
            float s1 = gamma[oc1] * rsqrtf(var[oc1] + BN_EPSF);
            g_shift2[gid] = make_float2(beta[oc0] - mean[oc0] * s0,
                                        beta[oc1] - mean[oc1] * s1);
        }
    } else {
        int gid = (bid - PREP_BLOCKS) * 256 + tid;
        if (gid < CC * NHP) {
            int k = gid / NHP, j = gid - (gid / NHP) * NHP;
            float2 v = make_float2(0.f, 0.f);
            if (j < NHID / 2)
                v = make_float2(w1[k * NHID + 2 * j], w1[k * NHID + 2 * j + 1]);
            g_w1p[gid] = v;
        }
        if (gid < NHP) {
            int j = gid;
            float2 bv = make_float2(0.f, 0.f), wv = make_float2(0.f, 0.f);
            if (j < NHID / 2) {
                bv = make_float2(b1[2 * j], b1[2 * j + 1]);
                wv = make_float2(w2[2 * j], w2[2 * j + 1]);
            }
            g_b1p[j] = bv;
            g_w2p[j] = wv;
        }
    }
}

// ---------------- conv inner: one ic, exact taps, acc[25] --------------------
__device__ __forceinline__ void conv_ic(const float* __restrict__ xr,
                                        const float2 w[9], float2 acc[25]) {
    #pragma unroll
    for (int iy = 0; iy < 5; iy++) {
        float xv[5];
        #pragma unroll
        for (int j = 0; j < 5; j++) xv[j] = xr[iy * 5 + j];
        #pragma unroll
        for (int oy = 0; oy < 5; oy++) {
            int ky = iy - oy + 1;
            if (ky >= 0 && ky <= 2) {
                #pragma unroll
                for (int ox = 0; ox < 5; ox++) {
                    #pragma unroll
                    for (int kx = 0; kx < 3; kx++) {
                        int j = ox - 1 + kx;
                        if (j >= 0 && j < 5) {
                            float v = xv[j];
                            acc[oy * 5 + ox] =
                                ffma2(w[ky * 3 + kx], make_float2(v, v), acc[oy * 5 + ox]);
                        }
                    }
                }
            }
        }
    }
}

// ---------------- K1: fused proto mean + conv (2 samples x 4 ic-chunks) ------
__global__ void __launch_bounds__(256) convp_kernel(const float* __restrict__ shot,
                                                    const float* __restrict__ pseudo) {
    __shared__ __align__(16) float sproto[2 * 1600];   // 12.8 KB
    __shared__ float2 red[2 * HWSZ * 32];              // 12.8 KB
    int tid = threadIdx.x;
    int lane = tid & 31;
    int warp = tid >> 5;
    int sl = warp >> 2;
    int chunk = warp & 3;
    int sBase = blockIdx.x * 2;

    for (int it = tid; it < 800; it += 256) {
        int s = it / 400;
        int j = it - s * 400;
        const float4* sh = (const float4*)(shot   + (size_t)(sBase + s) * NSHOT * 1600) + j;
        const float4* ps = (const float4*)(pseudo + (size_t)(sBase + s) * NSHOT * 1600) + j;
        float4 a = make_float4(0.f, 0.f, 0.f, 0.f);
        #pragma unroll
        for (int k = 0; k < NSHOT; k++) {
            float4 v = sh[k * 400];
            a.x += v.x; a.y += v.y; a.z += v.z; a.w += v.w;
        }
        #pragma unroll
        for (int k = 0; k < NSHOT; k++) {
            float4 v = ps[k * 400];
            a.x += v.x; a.y += v.y; a.z += v.z; a.w += v.w;
        }
        a.x *= 0.1f; a.y *= 0.1f; a.z *= 0.1f; a.w *= 0.1f;
        ((float4*)sproto)[it] = a;
    }
    __syncthreads();

    const float* xs = sproto + sl * 1600;
    float2 acc[25];
    #pragma unroll
    for (int i = 0; i < 25; i++) acc[i] = make_float2(0.f, 0.f);

    #pragma unroll 1
    for (int icl = 0; icl < 16; icl++) {
        int ic = chunk * 16 + icl;
        const float2* wr = g_wp2 + ic * 288 + lane;
        float2 w[9];
        #pragma unroll
        for (int k = 0; k < 9; k++) w[k] = wr[k * 32];
        conv_ic(xs + ic * 25, w, acc);
    }

    float2* rb = red + (sl * HWSZ) * 32 + lane;
    if (chunk == 0) {
        #pragma unroll
        for (int p = 0; p < 25; p++) rb[p * 32] = acc[p];
    }
    __syncthreads();
    if (chunk == 1) {
        #pragma unroll
        for (int p = 0; p < 25; p++) {
            float2 t = rb[p * 32]; t.x += acc[p].x; t.y += acc[p].y; rb[p * 32] = t;
        }
    }
    __syncthreads();
    if (chunk == 2) {
        #pragma unroll
        for (int p = 0; p < 25; p++) {
            float2 t = rb[p * 32]; t.x += acc[p].x; t.y += acc[p].y; rb[p * 32] = t;
        }
    }
    __syncthreads();
    if (chunk == 3) {
        float2 sh = g_shift2[lane];
        #pragma unroll
        for (int p = 0; p < 25; p++) {
            float2 t = rb[p * 32];
            t.x += acc[p].x + sh.x;
            t.y += acc[p].y + sh.y;
            g_cp[((sBase + sl) * HWSZ + p) * 32 + lane] = t;
        }
    }
}

// ---------------- K2: conv on queries — 4 warps/block, grid 600, balanced ----
__global__ void __launch_bounds__(128, 5) convq_kernel(const float* __restrict__ xq) {
    __shared__ __align__(16) float2 sw[8 * 9 * 32];    // 18.4 KB
    __shared__ __align__(16) float  sx[4 * 200];       // 3.2 KB
    int tid = threadIdx.x;
    int lane = tid & 31;
    int warp = tid >> 5;
    int s = blockIdx.x * 4 + warp;
    const float4* xsrc = (const float4*)(xq + (size_t)s * 1600);
    float* myx = sx + warp * 200;

    float2 acc[25];
    #pragma unroll
    for (int i = 0; i < 25; i++) acc[i] = make_float2(0.f, 0.f);

    #pragma unroll 1
    for (int ch = 0; ch < 8; ch++) {
        __syncthreads();   // protect previous chunk reads of sw/sx
        {
            const float4* src4 = (const float4*)(g_wq2 + ch * 8 * 288);
            float4* dst4 = (float4*)sw;
            #pragma unroll
            for (int i = 0; i < 9; i++)
                dst4[tid + i * 128] = src4[tid + i * 128];   // 1152 float4
        }
        {
            float4* dx = (float4*)myx;
            const float4* srcx = xsrc + ch * 50;
            dx[lane] = srcx[lane];
            if (lane < 18) dx[lane + 32] = srcx[lane + 32];
        }
        __syncthreads();
        #pragma unroll 1
        for (int icl = 0; icl < 8; icl++) {
            const float2* wr = sw + icl * 288 + lane;
            float2 w[9];
            #pragma unroll
            for (int k = 0; k < 9; k++) w[k] = wr[k * 32];
            conv_ic(myx + icl * 25, w, acc);
        }
    }

    int b = s / NQ;
    #pragma unroll 1
    for (int w = 0; w < NWAY; w++) {
        const float2* cp = g_cp + ((b * NWAY + w) * HWSZ) * 32 + lane;
        float ax = 0.f, ay = 0.f;
        #pragma unroll
        for (int p = 0; p < 25; p++) {
            float2 c = cp[p * 32];
            float x = acc[p].x + c.x; x = fmaxf(x, LEAK * x);
            float y = acc[p].y + c.y; y = fmaxf(y, LEAK * y);
            ax += x; ay += y;
        }
        ((float2*)g_feat)[((size_t)s * NWAY + w) * 32 + lane] =
            make_float2(ax * 0.04f, ay * 0.04f);
    }
}

// ---------------- K3: MLP — 48 rows/block (6 rows/thread), grid 250 ----------
#define MROWS 48
__global__ void __launch_bounds__(256, 2) mlp_kernel(const float* __restrict__ b2,
                                                     float* __restrict__ out) {
    __shared__ __align__(16) float  fsT[64][50];       // 12.8 KB (even pad: aligned f2)
    __shared__ __align__(16) float2 sw1[16 * NHP];     // 20 KB per chunk
    int tid = threadIdx.x;
    int tx = tid & 31;        // hidden-lane
    int ty = tid >> 5;        // row-group (6 rows each)
    int s0 = blockIdx.x * MROWS;

    for (int i = tid; i < MROWS * 64; i += 256) {
        int r = i >> 6, c = i & 63;
        fsT[c][r] = g_feat[(size_t)(s0 + r) * CC + c];
    }

    float2 acc[5][6];
    #pragma unroll
    for (int p = 0; p < 5; p++)
        #pragma unroll
        for (int r = 0; r < 6; r++) acc[p][r] = make_float2(0.f, 0.f);

    #pragma unroll 1
    for (int ch = 0; ch < 4; ch++) {
        __syncthreads();
        {
            const float4* src4 = (const float4*)(g_w1p + ch * 16 * NHP);
            float4* dst4 = (float4*)sw1;
            #pragma unroll
            for (int i = 0; i < 5; i++)
                dst4[tid + i * 256] = src4[tid + i * 256];
        }
        __syncthreads();
        #pragma unroll 2
        for (int kl = 0; kl < 16; kl++) {
            int k = ch * 16 + kl;
            float2 wv[5];
            #pragma unroll
            for (int p = 0; p < 5; p++) wv[p] = sw1[kl * NHP + tx + 32 * p];
            const float2* fr = (const float2*)&fsT[k][ty * 6];
            float2 f0 = fr[0], f1 = fr[1], f2 = fr[2];
            float fv[6] = {f0.x, f0.y, f1.x, f1.y, f2.x, f2.y};
            #pragma unroll
            for (int p = 0; p < 5; p++)
                #pragma unroll
                for (int r = 0; r < 6; r++)
                    acc[p][r] = ffma2(wv[p], make_float2(fv[r], fv[r]), acc[p][r]);
        }
    }

    float s[6];
    #pragma unroll
    for (int r = 0; r < 6; r++) s[r] = 0.f;
    #pragma unroll
    for (int p = 0; p < 5; p++) {
        float2 bv = g_b1p[tx + 32 * p];
        float2 wv = g_w2p[tx + 32 * p];
        #pragma unroll
        for (int r = 0; r < 6; r++) {
            float hx = acc[p][r].x + bv.x; hx = fmaxf(hx, LEAK * hx);
            float hy = acc[p][r].y + bv.y; hy = fmaxf(hy, LEAK * hy);
            s[r] += hx * wv.x + hy * wv.y;
        }
    }
    #pragma unroll
    for (int off = 16; off; off >>= 1)
        #pragma unroll
        for (int r = 0; r < 6; r++)
            s[r] += __shfl_down_sync(0xffffffffu, s[r], off);

    if (tx == 0) {
        float bb = b2[0];
        #pragma unroll
        for (int r = 0; r < 6; r++)
            out[s0 + ty * 6 + r] = 1.f / (1.f + expf(-(s[r] + bb)));
    }
}

// ---------------- launch -----------------------------------------------------
extern "C" void kernel_launch(void* const* d_in, const int* in_sizes, int n_in,
                              void* d_out, int out_size) {
    const float* x_shot   = (const float*)d_in[0];
    const float* x_pseudo = (const float*)d_in[1];
    const float* x_query  = (const float*)d_in[2];
    const float* conv_w   = (const float*)d_in[3];
    const float* bn_gamma = (const float*)d_in[4];
    const float* bn_beta  = (const float*)d_in[5];
    const float* bn_mean  = (const float*)d_in[6];
    const float* bn_var   = (const float*)d_in[7];
    const float* w1       = (const float*)d_in[8];
    const float* b1       = (const float*)d_in[9];
    const float* w2       = (const float*)d_in[10];
    const float* b2       = (const float*)d_in[11];
    float* out = (float*)d_out;

    prep_kernel<<<PREP_BLOCKS + MLPP_BLOCKS, 256>>>(
        conv_w, bn_gamma, bn_beta, bn_mean, bn_var, w1, b1, w2);
    convp_kernel<<<NSAMP_P / 2, 256>>>(x_shot, x_pseudo);
    convq_kernel<<<NSAMP_Q / 4, 128>>>(x_query);
    mlp_kernel<<<NPAIR / MROWS, 256>>>(b2, out);
}

// round 8
// speedup vs baseline: 1.4675x; 1.1575x over previous
#include <cuda_runtime.h>
#include <string.h>

#define LEAK 0.1f
#define BN_EPSF 1e-5f

#define BB     16
#define NWAY   5
#define NSHOT  5
#define NQ     150
#define CC     64
#define HWSZ   25
#define NSAMP_Q (BB*NQ)        // 2400
#define NSAMP_P (BB*NWAY)      // 80
#define NPAIR  (NSAMP_Q*NWAY)  // 12000
#define NHID   300
#define NHP    160             // padded hidden pairs

#define NPROTO_BLK 20
#define NQBLK      600
#define MROWS      24
#define NMLP_BLK   (NPAIR / MROWS)   // 500
#define GRID_MEGA  (NPROTO_BLK + NQBLK + NMLP_BLK)

// ---------------- scratch ----------------------------------------------------
__device__ __align__(16) float2 g_wq2[CC * 9 * 32];
__device__ __align__(16) float2 g_wp2[CC * 9 * 32];
__device__ float2 g_shift2[32];
__device__ float2 g_cp[NSAMP_P * HWSZ * 32];
__device__ float  g_feat[NPAIR * CC];
__device__ __align__(16) float2 g_w1p[CC * NHP];
__device__ float2 g_b1p[NHP];
__device__ float2 g_w2p[NHP];
__device__ int    g_protoCnt;
__device__ int    g_sflag[NSAMP_Q];

// ---------------- helpers ----------------------------------------------------
__device__ __forceinline__ float2 ffma2(float2 a, float2 b, float2 c) {
    unsigned long long A, B, C, D;
    memcpy(&A, &a, 8); memcpy(&B, &b, 8); memcpy(&C, &c, 8);
    asm("fma.rn.f32x2 %0, %1, %2, %3;" : "=l"(D) : "l"(A), "l"(B), "l"(C));
    float2 d; memcpy(&d, &D, 8);
    return d;
}

__device__ __forceinline__ void cpasync16(unsigned int dst, const void* src) {
    asm volatile("cp.async.cg.shared.global [%0], [%1], 16;\n" :: "r"(dst), "l"(src));
}
#define CP_COMMIT() asm volatile("cp.async.commit_group;\n")
#define CP_WAIT0()  asm volatile("cp.async.wait_group 0;\n")

__device__ __forceinline__ void conv_ic(const float* __restrict__ xr,
                                        const float2 w[9], float2 acc[25]) {
    #pragma unroll
    for (int iy = 0; iy < 5; iy++) {
        float xv[5];
        #pragma unroll
        for (int j = 0; j < 5; j++) xv[j] = xr[iy * 5 + j];
        #pragma unroll
        for (int oy = 0; oy < 5; oy++) {
            int ky = iy - oy + 1;
            if (ky >= 0 && ky <= 2) {
                #pragma unroll
                for (int ox = 0; ox < 5; ox++) {
                    #pragma unroll
                    for (int kx = 0; kx < 3; kx++) {
                        int j = ox - 1 + kx;
                        if (j >= 0 && j < 5) {
                            float v = xv[j];
                            acc[oy * 5 + ox] =
                                ffma2(w[ky * 3 + kx], make_float2(v, v), acc[oy * 5 + ox]);
                        }
                    }
                }
            }
        }
    }
}

// ---------------- K0: prep ---------------------------------------------------
#define PREP_BLOCKS 145
#define MLPP_BLOCKS 41
#define ZERO_BLOCKS 10
__global__ void prep_kernel(const float* __restrict__ cw,
                            const float* __restrict__ gamma,
                            const float* __restrict__ beta,
                            const float* __restrict__ mean,
                            const float* __restrict__ var,
                            const float* __restrict__ w1,
                            const float* __restrict__ b1,
                            const float* __restrict__ w2) {
    int bid = blockIdx.x;
    int tid = threadIdx.x;
    if (bid < PREP_BLOCKS) {
        int gid = bid * 256 + tid;
        const int total = CC * 9 * 32;
        if (gid < 2 * total) {
            int half = gid / total;
            int idx  = gid % total;
            int ic   = idx / (9 * 32);
            int k    = (idx / 32) % 9;
            int ocp  = idx & 31;
            int icf  = ic + half * 64;
            int oc0 = 2 * ocp, oc1 = oc0 + 1;
            float s0 = gamma[oc0] * rsqrtf(var[oc0] + BN_EPSF);
            float s1 = gamma[oc1] * rsqrtf(var[oc1] + BN_EPSF);
            float2 wv = make_float2(cw[(oc0 * 128 + icf) * 9 + k] * s0,
                                    cw[(oc1 * 128 + icf) * 9 + k] * s1);
            if (half) g_wp2[idx] = wv; else g_wq2[idx] = wv;
        }
        if (gid < 32) {
            int oc0 = 2 * gid, oc1 = oc0 + 1;
            float s0 = gamma[oc0] * rsqrtf(var[oc0] + BN_EPSF);
            float s1 = gamma[oc1] * rsqrtf(var[oc1] + BN_EPSF);
            g_shift2[gid] = make_float2(beta[oc0] - mean[oc0] * s0,
                                        beta[oc1] - mean[oc1] * s1);
        }
    } else if (bid < PREP_BLOCKS + MLPP_BLOCKS) {
        int gid = (bid - PREP_BLOCKS) * 256 + tid;
        if (gid < CC * NHP) {
            int k = gid / NHP, j = gid - (gid / NHP) * NHP;
            float2 v = make_float2(0.f, 0.f);
            if (j < NHID / 2)
                v = make_float2(w1[k * NHID + 2 * j], w1[k * NHID + 2 * j + 1]);
            g_w1p[gid] = v;
        }
        if (gid < NHP) {
            int j = gid;
            float2 bv = make_float2(0.f, 0.f), wv = make_float2(0.f, 0.f);
            if (j < NHID / 2) {
                bv = make_float2(b1[2 * j], b1[2 * j + 1]);
                wv = make_float2(w2[2 * j], w2[2 * j + 1]);
            }
            g_b1p[j] = bv;
            g_w2p[j] = wv;
        }
    } else {
        int gid = (bid - PREP_BLOCKS - MLPP_BLOCKS) * 256 + tid;
        if (gid < NSAMP_Q) g_sflag[gid] = 0;
        if (gid == 0) g_protoCnt = 0;
    }
}

// ---------------- mega kernel ------------------------------------------------
// smem layout (43264 B):
//   conv:  sw double buffer [0, 36864), sx double buffer [36864, 43264)
//   proto: sw single buffer [0, 18432), sx (buf 0)       [36864, 40064)
//   mlp:   sw1 [0, 20480), fsT [20480, 27648)
#define SMEM_BYTES 43264
__global__ void __launch_bounds__(128, 5) mega_kernel(
    const float* __restrict__ xq,
    const float* __restrict__ shot,
    const float* __restrict__ pseudo,
    const float* __restrict__ b2,
    float* __restrict__ out) {
    __shared__ __align__(16) unsigned char smem[SMEM_BYTES];
    int tid = threadIdx.x;
    int lane = tid & 31;
    int warp = tid >> 5;
    int bid = blockIdx.x;

    if (bid < NPROTO_BLK) {
        // ================= proto path ===================
        float2* sw = (float2*)smem;
        float*  sx = (float*)(smem + 36864);
        int s = bid * 4 + warp;               // 0..79
        float2 acc[25];
        #pragma unroll
        for (int i = 0; i < 25; i++) acc[i] = make_float2(0.f, 0.f);

        const float4* shp0 = ((const float4*)shot)   + (size_t)s * NSHOT * 400;
        const float4* psp0 = ((const float4*)pseudo) + (size_t)s * NSHOT * 400;

        #pragma unroll 1
        for (int ch = 0; ch < 8; ch++) {
            __syncthreads();
            {   // stage weights chunk (8 ics)
                const float4* src4 = (const float4*)(g_wp2 + ch * 2304);
                float4* dst4 = (float4*)sw;
                #pragma unroll
                for (int i = 0; i < 9; i++)
                    dst4[tid + i * 128] = src4[tid + i * 128];
            }
            {   // support mean for this warp's sample, 8 ics
                float4* dx = (float4*)(sx + warp * 200);
                for (int j = lane; j < 50; j += 32) {
                    float4 a = make_float4(0.f, 0.f, 0.f, 0.f);
                    #pragma unroll
                    for (int k = 0; k < NSHOT; k++) {
                        float4 v = shp0[k * 400 + ch * 50 + j];
                        a.x += v.x; a.y += v.y; a.z += v.z; a.w += v.w;
                    }
                    #pragma unroll
                    for (int k = 0; k < NSHOT; k++) {
                        float4 v = psp0[k * 400 + ch * 50 + j];
                        a.x += v.x; a.y += v.y; a.z += v.z; a.w += v.w;
                    }
                    a.x *= 0.1f; a.y *= 0.1f; a.z *= 0.1f; a.w *= 0.1f;
                    dx[j] = a;
                }
            }
            __syncthreads();
            #pragma unroll 1
            for (int icl = 0; icl < 8; icl++) {
                float2 w[9];
                #pragma unroll
                for (int k = 0; k < 9; k++) w[k] = sw[icl * 288 + lane + k * 32];
                conv_ic(sx + warp * 200 + icl * 25, w, acc);
            }
        }
        float2 sh = g_shift2[lane];
        #pragma unroll
        for (int p = 0; p < 25; p++) {
            float2 t = acc[p];
            t.x += sh.x; t.y += sh.y;
            g_cp[(s * HWSZ + p) * 32 + lane] = t;
        }
        __syncwarp();
        __threadfence();
        if (lane == 0) atomicAdd(&g_protoCnt, 1);
    } else if (bid < NPROTO_BLK + NQBLK) {
        // ================= query path ===================
        int s = (bid - NPROTO_BLK) * 4 + warp;    // 0..2399
        const float4* xsrc = (const float4*)(xq + (size_t)s * 1600);
        unsigned int smu = (unsigned int)__cvta_generic_to_shared(smem);

        float2 acc[25];
        #pragma unroll
        for (int i = 0; i < 25; i++) acc[i] = make_float2(0.f, 0.f);

        // prologue: chunk 0 into buf 0
        {
            const float4* wsrc = ((const float4*)g_wq2);
            #pragma unroll
            for (int i = 0; i < 9; i++)
                cpasync16(smu + (tid + i * 128) * 16, wsrc + tid + i * 128);
            unsigned int xdst = smu + 36864 + warp * 800;
            cpasync16(xdst + lane * 16, xsrc + lane);
            if (lane < 18) cpasync16(xdst + (lane + 32) * 16, xsrc + lane + 32);
            CP_COMMIT();
            CP_WAIT0();
        }
        __syncthreads();

        #pragma unroll 1
        for (int ch = 0; ch < 8; ch++) {
            int buf = ch & 1;
            if (ch < 7) {
                int nb = buf ^ 1;
                const float4* wsrc = ((const float4*)g_wq2) + (ch + 1) * 1152;
                unsigned int wdst = smu + nb * 18432;
                #pragma unroll
                for (int i = 0; i < 9; i++)
                    cpasync16(wdst + (tid + i * 128) * 16, wsrc + tid + i * 128);
                const float4* xs = xsrc + (ch + 1) * 50;
                unsigned int xdst = smu + 36864 + nb * 3200 + warp * 800;
                cpasync16(xdst + lane * 16, xs + lane);
                if (lane < 18) cpasync16(xdst + (lane + 32) * 16, xs + lane + 32);
                CP_COMMIT();
            }
            const float2* swb = (const float2*)(smem + buf * 18432);
            const float* myx = (const float*)(smem + 36864 + buf * 3200 + warp * 800);
            #pragma unroll 1
            for (int icl = 0; icl < 8; icl++) {
                float2 w[9];
                #pragma unroll
                for (int k = 0; k < 9; k++) w[k] = swb[icl * 288 + lane + k * 32];
                conv_ic(myx + icl * 25, w, acc);
            }
            if (ch < 7) {
                CP_WAIT0();
                __syncthreads();
            }
        }

        // wait for protos
        if (tid == 0) {
            while (*(volatile int*)&g_protoCnt < NSAMP_P) __nanosleep(64);
        }
        __syncthreads();

        int b = s / NQ;
        #pragma unroll 1
        for (int w = 0; w < NWAY; w++) {
            const float2* cp = g_cp + ((b * NWAY + w) * HWSZ) * 32 + lane;
            float ax = 0.f, ay = 0.f;
            #pragma unroll
            for (int p = 0; p < 25; p++) {
                float2 c = __ldcg(cp + p * 32);
                float x = acc[p].x + c.x; x = fmaxf(x, LEAK * x);
                float y = acc[p].y + c.y; y = fmaxf(y, LEAK * y);
                ax += x; ay += y;
            }
            ((float2*)g_feat)[((size_t)s * NWAY + w) * 32 + lane] =
                make_float2(ax * 0.04f, ay * 0.04f);
        }
        __syncwarp();
        __threadfence();
        if (lane == 0) *(volatile int*)&g_sflag[s] = 1;
    } else {
        // ================= mlp path ===================
        int t = bid - NPROTO_BLK - NQBLK;
        int s0 = t * MROWS;
        int smin = s0 / NWAY, smax = (s0 + MROWS - 1) / NWAY;
        if (tid == 0) {
            for (int ss = smin; ss <= smax; ss++)
                while (*(volatile int*)&g_sflag[ss] == 0) __nanosleep(64);
        }
        __syncthreads();

        float2* sw1 = (float2*)smem;                 // 16k x 160 hp
        float*  fsT = (float*)(smem + 20480);        // [64][28]

        for (int i = tid; i < MROWS * 64; i += 128) {
            int r = i >> 6, c = i & 63;
            fsT[c * 28 + r] = __ldcg(&g_feat[(size_t)(s0 + r) * CC + c]);
        }

        float2 acc[5][6];
        #pragma unroll
        for (int p = 0; p < 5; p++)
            #pragma unroll
            for (int r = 0; r < 6; r++) acc[p][r] = make_float2(0.f, 0.f);

        #pragma unroll 1
        for (int ch = 0; ch < 4; ch++) {
            __syncthreads();
            {
                const float4* src4 = (const float4*)(g_w1p + ch * 16 * NHP);
                float4* dst4 = (float4*)sw1;
                #pragma unroll
                for (int i = 0; i < 10; i++)
                    dst4[tid + i * 128] = src4[tid + i * 128];
            }
            __syncthreads();
            #pragma unroll 2
            for (int kl = 0; kl < 16; kl++) {
                int k = ch * 16 + kl;
                float2 wv[5];
                #pragma unroll
                for (int p = 0; p < 5; p++) wv[p] = sw1[kl * NHP + lane + 32 * p];
                const float2* fr = (const float2*)&fsT[k * 28 + warp * 6];
                float2 f0 = fr[0], f1 = fr[1], f2 = fr[2];
                float fv[6] = {f0.x, f0.y, f1.x, f1.y, f2.x, f2.y};
                #pragma unroll
                for (int p = 0; p < 5; p++)
                    #pragma unroll
                    for (int r = 0; r < 6; r++)
                        acc[p][r] = ffma2(wv[p], make_float2(fv[r], fv[r]), acc[p][r]);
            }
        }

        float sr[6];
        #pragma unroll
        for (int r = 0; r < 6; r++) sr[r] = 0.f;
        #pragma unroll
        for (int p = 0; p < 5; p++) {
            float2 bv = g_b1p[lane + 32 * p];
            float2 wv = g_w2p[lane + 32 * p];
            #pragma unroll
            for (int r = 0; r < 6; r++) {
                float hx = acc[p][r].x + bv.x; hx = fmaxf(hx, LEAK * hx);
                float hy = acc[p][r].y + bv.y; hy = fmaxf(hy, LEAK * hy);
                sr[r] += hx * wv.x + hy * wv.y;
            }
        }
        #pragma unroll
        for (int off = 16; off; off >>= 1)
            #pragma unroll
            for (int r = 0; r < 6; r++)
                sr[r] += __shfl_down_sync(0xffffffffu, sr[r], off);

        if (lane == 0) {
            float bb = b2[0];
            #pragma unroll
            for (int r = 0; r < 6; r++)
                out[s0 + warp * 6 + r] = 1.f / (1.f + expf(-(sr[r] + bb)));
        }
    }
}

// ---------------- launch -----------------------------------------------------
extern "C" void kernel_launch(void* const* d_in, const int* in_sizes, int n_in,
                              void* d_out, int out_size) {
    const float* x_shot   = (const float*)d_in[0];
    const float* x_pseudo = (const float*)d_in[1];
    const float* x_query  = (const float*)d_in[2];
    const float* conv_w   = (const float*)d_in[3];
    const float* bn_gamma = (const float*)d_in[4];
    const float* bn_beta  = (const float*)d_in[5];
    const float* bn_mean  = (const float*)d_in[6];
    const float* bn_var   = (const float*)d_in[7];
    const float* w1       = (const float*)d_in[8];
    const float* b1       = (const float*)d_in[9];
    const float* w2       = (const float*)d_in[10];
    const float* b2       = (const float*)d_in[11];
    float* out = (float*)d_out;

    prep_kernel<<<PREP_BLOCKS + MLPP_BLOCKS + ZERO_BLOCKS, 256>>>(
        conv_w, bn_gamma, bn_beta, bn_mean, bn_var, w1, b1, w2);
    mega_kernel<<<GRID_MEGA, 128>>>(x_query, x_shot, x_pseudo, b2, out);
}